// round 4
// baseline (speedup 1.0000x reference)
#include <cuda_runtime.h>
#include <cuda_bf16.h>
#include <cstdint>

// ---------------------------------------------------------------------------
// PhaseTracker: encode -> evolve -> similarity GEMM (f32x2) -> parallel greedy
// R1-proven data layouts: A flat [c-pairs | s-pairs], B flat [cos rows | sin rows]
// ---------------------------------------------------------------------------

#define N_DET   4096
#define DIM     128
#define HID     64
#define NOSC    28
#define KTOT    56
#define TWO_PI_F 6.283185307179586f
#define INV_2PI  0.15915494309189535f
#define DENOM_F  28.000010583006244f   // (sqrt(28)+1e-6)^2

__device__ float g_phase[N_DET * NOSC];
__device__ float g_amp[N_DET * NOSC];
__device__ float g_A[N_DET * 112];          // row: [c0 c0 c1 c1 .. c27 c27 | s0 s0 .. s27 s27]
__device__ float g_B[KTOT * N_DET];         // rows 0..27 = cos_k, rows 28..55 = sin_k
__device__ unsigned long long g_rowbest[N_DET];
__device__ unsigned long long g_colbest[N_DET];

__device__ __forceinline__ float mod2pi(float v) {
    return v - floorf(v * INV_2PI) * TWO_PI_F;
}
__device__ __forceinline__ float softplusf(float x) {
    return fmaxf(x, 0.0f) + log1pf(expf(-fabsf(x)));
}
__device__ __forceinline__ unsigned ordf(float x) {
    unsigned u = __float_as_uint(x);
    return (u & 0x80000000u) ? ~u : (u | 0x80000000u);
}
__device__ __forceinline__ void ffma2(unsigned long long& d,
                                      unsigned long long a,
                                      unsigned long long b) {
    asm("fma.rn.f32x2 %0, %1, %2, %0;" : "+l"(d) : "l"(a), "l"(b));
}

// ---------------------------------------------------------------------------
__global__ void init_kernel() {
    int i = blockIdx.x * blockDim.x + threadIdx.x;
    if (i < N_DET) { g_rowbest[i] = 0ull; g_colbest[i] = 0ull; }
}

// ---------------------------------------------------------------------------
// Encode (R1-proven structure; only change: 2-way ILP accumulators).
// 256 threads, 32 rows per block (2 rows per inner iteration).
// ---------------------------------------------------------------------------
#define ENC_W1STR 132
#define ENC_W2STR 68
#define ENC_SMEM_FLOATS (2*HID*ENC_W1STR + 2*NOSC*ENC_W2STR + 256 + 256)

__global__ __launch_bounds__(256, 2)
void encode_kernel(const float* __restrict__ det_t, const float* __restrict__ det_t1,
                   const float* __restrict__ Wp1, const float* __restrict__ bp1,
                   const float* __restrict__ Wp2, const float* __restrict__ bp2,
                   const float* __restrict__ Wa1, const float* __restrict__ ba1,
                   const float* __restrict__ Wa2, const float* __restrict__ ba2) {
    extern __shared__ float sm[];
    float* wp1T = sm;                          // HID x ENC_W1STR
    float* wa1T = wp1T + HID * ENC_W1STR;
    float* wp2T = wa1T + HID * ENC_W1STR;      // NOSC x ENC_W2STR
    float* wa2T = wp2T + NOSC * ENC_W2STR;
    float* xs   = wa2T + NOSC * ENC_W2STR;     // 2 x 128
    float* hs   = xs + 256;                    // 2 x 128  (h | ha per row)

    int tid = threadIdx.x;
    for (int idx = tid; idx < DIM * HID; idx += 256) {
        int k = idx >> 6, j = idx & 63;
        wp1T[j * ENC_W1STR + k] = Wp1[idx];
        wa1T[j * ENC_W1STR + k] = Wa1[idx];
    }
    for (int idx = tid; idx < HID * NOSC; idx += 256) {
        int k = idx / NOSC, j = idx % NOSC;
        wp2T[j * ENC_W2STR + k] = Wp2[idx];
        wa2T[j * ENC_W2STR + k] = Wa2[idx];
    }

    int hf = tid >> 7;          // which of the 2 rows this thread serves
    int t  = tid & 127;

    for (int it = 0; it < 16; ++it) {
        int row = blockIdx.x * 32 + it * 2 + hf;
        bool isT = row < N_DET;
        const float* X = isT ? (det_t + (size_t)row * DIM)
                             : (det_t1 + (size_t)(row - N_DET) * DIM);
        __syncthreads();                 // protect xs/hs from previous iter
        xs[hf * 128 + t] = X[t];
        __syncthreads();

        // layer 1: t<64 -> phase h, t>=64 -> amp ha (amp only for t rows)
        {
            bool doAmp = (t >= 64);
            if (!doAmp || isT) {
                int j = doAmp ? (t - 64) : t;
                const float4* w4 = (const float4*)(doAmp ? &wa1T[j * ENC_W1STR]
                                                         : &wp1T[j * ENC_W1STR]);
                const float4* x4 = (const float4*)(xs + hf * 128);
                float acc0 = doAmp ? ba1[j] : bp1[j];
                float acc1 = 0.0f;
                #pragma unroll
                for (int k4 = 0; k4 < 32; k4 += 2) {
                    float4 w = w4[k4], x = x4[k4];
                    acc0 += w.x * x.x + w.y * x.y + w.z * x.z + w.w * x.w;
                    float4 w2 = w4[k4 + 1], x2 = x4[k4 + 1];
                    acc1 += w2.x * x2.x + w2.y * x2.y + w2.z * x2.z + w2.w * x2.w;
                }
                hs[hf * 128 + t] = fmaxf(acc0 + acc1, 0.0f);
            }
        }
        __syncthreads();

        // layer 2
        int lane = t & 31, wgrp = t >> 5;
        if (wgrp == 0 && lane < NOSC) {               // phase head
            const float4* w4 = (const float4*)&wp2T[lane * ENC_W2STR];
            const float4* h4 = (const float4*)(hs + hf * 128);
            float acc0 = bp2[lane], acc1 = 0.0f;
            #pragma unroll
            for (int k4 = 0; k4 < 16; k4 += 2) {
                float4 w = w4[k4], h = h4[k4];
                acc0 += w.x * h.x + w.y * h.y + w.z * h.z + w.w * h.w;
                float4 w2 = w4[k4 + 1], h2 = h4[k4 + 1];
                acc1 += w2.x * h2.x + w2.y * h2.y + w2.z * h2.z + w2.w * h2.w;
            }
            float ph = mod2pi(acc0 + acc1);
            if (isT) {
                g_phase[row * NOSC + lane] = ph;
            } else {
                int col = row - N_DET;
                g_B[lane * N_DET + col]          = cosf(ph);
                g_B[(lane + NOSC) * N_DET + col] = sinf(ph);
            }
        } else if (wgrp == 1 && lane < NOSC && isT) { // amp head (t rows only)
            const float4* w4 = (const float4*)&wa2T[lane * ENC_W2STR];
            const float4* h4 = (const float4*)(hs + hf * 128 + 64);
            float acc0 = ba2[lane], acc1 = 0.0f;
            #pragma unroll
            for (int k4 = 0; k4 < 16; k4 += 2) {
                float4 w = w4[k4], h = h4[k4];
                acc0 += w.x * h.x + w.y * h.y + w.z * h.z + w.w * h.w;
                float4 w2 = w4[k4 + 1], h2 = h4[k4 + 1];
                acc1 += w2.x * h2.x + w2.y * h2.y + w2.z * h2.z + w2.w * h2.w;
            }
            g_amp[row * NOSC + lane] = softplusf(acc0 + acc1);
        }
    }
}

// ---------------------------------------------------------------------------
// Evolve: 5 Kuramoto steps, one warp per row. Writes flat A (R1 layout).
// ---------------------------------------------------------------------------
__global__ void evolve_kernel() {
    int gw   = (blockIdx.x * blockDim.x + threadIdx.x) >> 5;
    int lane = threadIdx.x & 31;
    if (gw >= N_DET) return;
    bool act = lane < NOSC;

    float ph = act ? g_phase[gw * NOSC + lane] : 0.0f;
    float am = act ? g_amp[gw * NOSC + lane] : 0.0f;
    float omega = TWO_PI_F * (lane < 4 ? 2.0f : (lane < 12 ? 6.0f : 40.0f));

    #pragma unroll
    for (int s = 0; s < 5; ++s) {
        float c  = act ? cosf(ph) : 0.0f;
        float sn = act ? sinf(ph) : 0.0f;
        float sc = c, ss = sn;
        #pragma unroll
        for (int off = 16; off; off >>= 1) {
            sc += __shfl_down_sync(0xFFFFFFFFu, sc, off);
            ss += __shfl_down_sync(0xFFFFFFFFu, ss, off);
        }
        sc = __shfl_sync(0xFFFFFFFFu, sc, 0);
        ss = __shfl_sync(0xFFFFFFFFu, ss, 0);
        float mc = sc / 28.0f, ms = ss / 28.0f;
        float coup = ms * c - mc * sn;
        ph = mod2pi(ph + 0.01f * (omega + am * coup));
    }
    if (act) {
        float c = cosf(ph), sn = sinf(ph);
        float* arow = g_A + (size_t)gw * 112;
        arow[2 * lane]     = c;  arow[2 * lane + 1]    = c;
        arow[56 + 2*lane]  = sn; arow[56 + 2*lane + 1] = sn;
    }
}

// ---------------------------------------------------------------------------
// Similarity GEMM: widened R1 kernel. 128x256 tile per block, 256 threads.
// Identical index math to the PASSING R1 gemm; only the column tile is 256
// (4 sections of 64) instead of 128 (2 sections).
// Flat pairing: A pair index m (ulonglong at 2m floats... via 4*kp picking
// pairs 2kp,2kp+1) multiplies B rows 2kp,2kp+1 — valid for any m since
// pair m and row m refer to the same (cos/sin, oscillator) element.
// ---------------------------------------------------------------------------
#define GEMM_SMEM_BYTES ((128*112 + 56*256) * 4)

__global__ __launch_bounds__(256, 1)
void gemm_kernel(float* __restrict__ sim) {
    extern __shared__ float smg[];
    float* As = smg;                 // 128 rows x 112 (flat dup pairs)
    float* Bs = smg + 128 * 112;     // 56 k-rows x 256 cols (flat)

    const int tid = threadIdx.x;
    const int tx = tid & 31;
    const int ty = tid >> 5;         // 8 warps -> 8 row groups of 16

    {
        const float4* gA = (const float4*)(g_A + (size_t)blockIdx.y * 128 * 112);
        float4* sA = (float4*)As;
        #pragma unroll
        for (int i = 0; i < 14; ++i) sA[tid + i * 256] = gA[tid + i * 256];

        float4* sB = (float4*)Bs;
        #pragma unroll
        for (int i = 0; i < 14; ++i) {
            int idx = tid + i * 256;            // 0..3583
            int k = idx >> 6, jq = idx & 63;
            sB[idx] = *(const float4*)(g_B + (size_t)k * N_DET + blockIdx.x * 256 + jq * 4);
        }
    }
    __syncthreads();

    unsigned long long acc[16][4];
    #pragma unroll
    for (int r = 0; r < 16; ++r)
        #pragma unroll
        for (int s = 0; s < 4; ++s) acc[r][s] = 0ull;

    #pragma unroll 2
    for (int kp = 0; kp < 28; ++kp) {
        const float* b0 = Bs + (2 * kp) * 256;       // flat row 2kp
        const float* b1 = b0 + 256;                  // flat row 2kp+1
        unsigned long long bc[4], bs[4];
        #pragma unroll
        for (int s = 0; s < 4; ++s) {
            bc[s] = *(const unsigned long long*)(b0 + s * 64 + tx * 2);
            bs[s] = *(const unsigned long long*)(b1 + s * 64 + tx * 2);
        }
        #pragma unroll
        for (int r = 0; r < 16; ++r) {
            ulonglong2 av = *(const ulonglong2*)(As + (ty * 16 + r) * 112 + 4 * kp);
            #pragma unroll
            for (int s = 0; s < 4; ++s) {
                ffma2(acc[r][s], av.x, bc[s]);
                ffma2(acc[r][s], av.y, bs[s]);
            }
        }
    }

    const float invden = 1.0f / DENOM_F;
    #pragma unroll
    for (int r = 0; r < 16; ++r) {
        int grow = blockIdx.y * 128 + ty * 16 + r;
        unsigned long long best = 0ull;
        #pragma unroll
        for (int s = 0; s < 4; ++s) {
            float2 v = *(float2*)&acc[r][s];
            v.x *= invden; v.y *= invden;
            int gcol = blockIdx.x * 256 + s * 64 + tx * 2;
            *(float2*)(sim + (size_t)grow * N_DET + gcol) = v;
            unsigned long long k0 = ((unsigned long long)ordf(v.x) << 32) | (unsigned)(~(unsigned)gcol);
            unsigned long long k1 = ((unsigned long long)ordf(v.y) << 32) | (unsigned)(~(unsigned)(gcol + 1));
            unsigned long long kk = (k0 > k1) ? k0 : k1;
            if (kk > best) best = kk;
        }
        #pragma unroll
        for (int off = 16; off; off >>= 1) {
            unsigned long long o = __shfl_down_sync(0xFFFFFFFFu, best, off);
            if (o > best) best = o;
        }
        if (tx == 0) atomicMax(&g_rowbest[grow], best);
    }
}

// ---------------------------------------------------------------------------
// Parallel greedy match (exact equivalent of the sequential scan).
// ---------------------------------------------------------------------------
__global__ void claim_kernel() {
    int i = blockIdx.x * blockDim.x + threadIdx.x;
    if (i >= N_DET) return;
    const unsigned ORD_THR = __float_as_uint(0.3f) | 0x80000000u;
    unsigned long long rb = g_rowbest[i];
    unsigned ordsim = (unsigned)(rb >> 32);
    if (ordsim > ORD_THR) {
        unsigned j = ~(unsigned)rb;
        unsigned long long claimkey = (rb & 0xFFFFFFFF00000000ull) | (unsigned)(~(unsigned)i);
        atomicMax(&g_colbest[j], claimkey);
    }
}

__global__ void resolve_kernel(float* __restrict__ matches) {
    int i = blockIdx.x * blockDim.x + threadIdx.x;
    if (i >= N_DET) return;
    const unsigned ORD_THR = __float_as_uint(0.3f) | 0x80000000u;
    unsigned long long rb = g_rowbest[i];
    unsigned ordsim = (unsigned)(rb >> 32);
    float m = -1.0f;
    if (ordsim > ORD_THR) {
        unsigned j = ~(unsigned)rb;
        unsigned long long claimkey = (rb & 0xFFFFFFFF00000000ull) | (unsigned)(~(unsigned)i);
        if (g_colbest[j] == claimkey) m = (float)j;
    }
    matches[i] = m;
}

// ---------------------------------------------------------------------------
extern "C" void kernel_launch(void* const* d_in, const int* in_sizes, int n_in,
                              void* d_out, int out_size) {
    const float* det_t  = (const float*)d_in[0];
    const float* det_t1 = (const float*)d_in[1];
    const float* Wp1 = (const float*)d_in[2];
    const float* bp1 = (const float*)d_in[3];
    const float* Wp2 = (const float*)d_in[4];
    const float* bp2 = (const float*)d_in[5];
    const float* Wa1 = (const float*)d_in[6];
    const float* ba1 = (const float*)d_in[7];
    const float* Wa2 = (const float*)d_in[8];
    const float* ba2 = (const float*)d_in[9];
    float* out = (float*)d_out;                 // [0,4096): matches, then sim

    cudaFuncSetAttribute(encode_kernel, cudaFuncAttributeMaxDynamicSharedMemorySize,
                         ENC_SMEM_FLOATS * 4);
    cudaFuncSetAttribute(gemm_kernel, cudaFuncAttributeMaxDynamicSharedMemorySize,
                         GEMM_SMEM_BYTES);

    init_kernel<<<16, 256>>>();
    encode_kernel<<<256, 256, ENC_SMEM_FLOATS * 4>>>(det_t, det_t1,
                                                     Wp1, bp1, Wp2, bp2,
                                                     Wa1, ba1, Wa2, ba2);
    evolve_kernel<<<512, 256>>>();
    gemm_kernel<<<dim3(16, 32), 256, GEMM_SMEM_BYTES>>>(out + N_DET);
    claim_kernel<<<16, 256>>>();
    resolve_kernel<<<16, 256>>>(out);
}

// round 5
// speedup vs baseline: 1.1904x; 1.1904x over previous
#include <cuda_runtime.h>
#include <cuda_bf16.h>
#include <cstdint>

// ---------------------------------------------------------------------------
// PhaseTracker: encode -> evolve -> similarity GEMM (f32x2) -> parallel greedy
// Proven layouts: A flat [c-pairs | s-pairs], B flat [cos rows | sin rows]
// ---------------------------------------------------------------------------

#define N_DET   4096
#define DIM     128
#define HID     64
#define NOSC    28
#define KTOT    56
#define TWO_PI_F 6.283185307179586f
#define INV_2PI  0.15915494309189535f
#define DENOM_F  28.000010583006244f   // (sqrt(28)+1e-6)^2

__device__ float g_phase[N_DET * NOSC];
__device__ float g_amp[N_DET * NOSC];
__device__ float g_A[N_DET * 112];          // row: [c0 c0 c1 c1 .. c27 c27 | s0 s0 .. s27 s27]
__device__ float g_B[KTOT * N_DET];         // rows 0..27 = cos_k, rows 28..55 = sin_k
__device__ unsigned long long g_rowbest[N_DET];
__device__ unsigned long long g_colbest[N_DET];

__device__ __forceinline__ float mod2pi(float v) {
    return v - floorf(v * INV_2PI) * TWO_PI_F;
}
__device__ __forceinline__ float softplusf(float x) {
    return fmaxf(x, 0.0f) + log1pf(expf(-fabsf(x)));
}
__device__ __forceinline__ unsigned ordf(float x) {
    unsigned u = __float_as_uint(x);
    return (u & 0x80000000u) ? ~u : (u | 0x80000000u);
}
__device__ __forceinline__ void ffma2(unsigned long long& d,
                                      unsigned long long a,
                                      unsigned long long b) {
    asm("fma.rn.f32x2 %0, %1, %2, %0;" : "+l"(d) : "l"(a), "l"(b));
}

// ---------------------------------------------------------------------------
__global__ void init_kernel() {
    int i = blockIdx.x * blockDim.x + threadIdx.x;
    if (i < N_DET) { g_rowbest[i] = 0ull; g_colbest[i] = 0ull; }
}

// ---------------------------------------------------------------------------
// Encode: R1 thread mapping (t = out index, strided w4 reads) but each thread
// now computes TWO rows per weight read (weight amortization x2).
// 256 threads, 32 rows per block, 8 iterations of 4 rows.
//   quad = tid>>7 in {0,1} -> local rows 2*quad, 2*quad+1
//   t    = tid&127: t<64 -> phase out t, t>=64 -> amp out t-64
// ---------------------------------------------------------------------------
#define ENC_W1STR 132
#define ENC_W2STR 68
#define ENC_SMEM_FLOATS (2*HID*ENC_W1STR + 2*NOSC*ENC_W2STR + 512 + 512)

__global__ __launch_bounds__(256, 2)
void encode_kernel(const float* __restrict__ det_t, const float* __restrict__ det_t1,
                   const float* __restrict__ Wp1, const float* __restrict__ bp1,
                   const float* __restrict__ Wp2, const float* __restrict__ bp2,
                   const float* __restrict__ Wa1, const float* __restrict__ ba1,
                   const float* __restrict__ Wa2, const float* __restrict__ ba2) {
    extern __shared__ float sm[];
    float* wp1T = sm;                          // HID x ENC_W1STR
    float* wa1T = wp1T + HID * ENC_W1STR;
    float* wp2T = wa1T + HID * ENC_W1STR;      // NOSC x ENC_W2STR
    float* wa2T = wp2T + NOSC * ENC_W2STR;
    float* xs   = wa2T + NOSC * ENC_W2STR;     // 4 x 128
    float* hs   = xs + 512;                    // 4 x 128  (h | ha per row)

    int tid = threadIdx.x;
    for (int idx = tid; idx < DIM * HID; idx += 256) {
        int k = idx >> 6, j = idx & 63;
        wp1T[j * ENC_W1STR + k] = Wp1[idx];
        wa1T[j * ENC_W1STR + k] = Wa1[idx];
    }
    for (int idx = tid; idx < HID * NOSC; idx += 256) {
        int k = idx / NOSC, j = idx % NOSC;
        wp2T[j * ENC_W2STR + k] = Wp2[idx];
        wa2T[j * ENC_W2STR + k] = Wa2[idx];
    }

    const int quad = tid >> 7;          // row pair selector
    const int t    = tid & 127;
    const int r0 = 2 * quad, r1 = r0 + 1;   // local rows in the 4-row group

    for (int it = 0; it < 8; ++it) {
        int rowbase = blockIdx.x * 32 + it * 4;
        bool isT = rowbase < N_DET;
        const float* X = isT ? (det_t + (size_t)rowbase * DIM)
                             : (det_t1 + (size_t)(rowbase - N_DET) * DIM);
        __syncthreads();                 // protect xs/hs from previous iter
        if (tid < 128) {
            ((float4*)xs)[tid] = ((const float4*)X)[tid];   // 4 rows x 128 floats
        }
        __syncthreads();

        // layer 1: t<64 -> phase h, t>=64 -> amp ha (amp only for t rows)
        {
            bool doAmp = (t >= 64);
            if (!doAmp || isT) {
                int j = doAmp ? (t - 64) : t;
                const float4* w4 = (const float4*)(doAmp ? &wa1T[j * ENC_W1STR]
                                                         : &wp1T[j * ENC_W1STR]);
                const float4* x0 = (const float4*)(xs + r0 * 128);
                const float4* x1 = (const float4*)(xs + r1 * 128);
                float b = doAmp ? ba1[j] : bp1[j];
                float a0 = b, a1 = b, c0 = 0.0f, c1 = 0.0f;
                #pragma unroll
                for (int k4 = 0; k4 < 32; k4 += 2) {
                    float4 w = w4[k4];
                    float4 xa = x0[k4], xb = x1[k4];
                    a0 += w.x * xa.x + w.y * xa.y + w.z * xa.z + w.w * xa.w;
                    a1 += w.x * xb.x + w.y * xb.y + w.z * xb.z + w.w * xb.w;
                    float4 w2 = w4[k4 + 1];
                    float4 xc = x0[k4 + 1], xd = x1[k4 + 1];
                    c0 += w2.x * xc.x + w2.y * xc.y + w2.z * xc.z + w2.w * xc.w;
                    c1 += w2.x * xd.x + w2.y * xd.y + w2.z * xd.z + w2.w * xd.w;
                }
                hs[r0 * 128 + t] = fmaxf(a0 + c0, 0.0f);
                hs[r1 * 128 + t] = fmaxf(a1 + c1, 0.0f);
            }
        }
        __syncthreads();

        // layer 2 (two rows per thread as well)
        int lane = t & 31, wgrp = t >> 5;
        if (wgrp == 0 && lane < NOSC) {               // phase head, rows r0,r1
            const float4* w4 = (const float4*)&wp2T[lane * ENC_W2STR];
            const float4* h0 = (const float4*)(hs + r0 * 128);
            const float4* h1 = (const float4*)(hs + r1 * 128);
            float b = bp2[lane];
            float p0 = b, p1 = b, q0 = 0.0f, q1 = 0.0f;
            #pragma unroll
            for (int k4 = 0; k4 < 16; k4 += 2) {
                float4 w = w4[k4];
                float4 ha = h0[k4], hb = h1[k4];
                p0 += w.x * ha.x + w.y * ha.y + w.z * ha.z + w.w * ha.w;
                p1 += w.x * hb.x + w.y * hb.y + w.z * hb.z + w.w * hb.w;
                float4 w2 = w4[k4 + 1];
                float4 hc = h0[k4 + 1], hd = h1[k4 + 1];
                q0 += w2.x * hc.x + w2.y * hc.y + w2.z * hc.z + w2.w * hc.w;
                q1 += w2.x * hd.x + w2.y * hd.y + w2.z * hd.z + w2.w * hd.w;
            }
            float ph0 = mod2pi(p0 + q0), ph1 = mod2pi(p1 + q1);
            int gr0 = rowbase + r0, gr1 = rowbase + r1;
            if (isT) {
                g_phase[gr0 * NOSC + lane] = ph0;
                g_phase[gr1 * NOSC + lane] = ph1;
            } else {
                int cc0 = gr0 - N_DET, cc1 = gr1 - N_DET;
                g_B[lane * N_DET + cc0]          = cosf(ph0);
                g_B[(lane + NOSC) * N_DET + cc0] = sinf(ph0);
                g_B[lane * N_DET + cc1]          = cosf(ph1);
                g_B[(lane + NOSC) * N_DET + cc1] = sinf(ph1);
            }
        } else if (wgrp == 1 && lane < NOSC && isT) { // amp head, rows r0,r1
            const float4* w4 = (const float4*)&wa2T[lane * ENC_W2STR];
            const float4* h0 = (const float4*)(hs + r0 * 128 + 64);
            const float4* h1 = (const float4*)(hs + r1 * 128 + 64);
            float b = ba2[lane];
            float p0 = b, p1 = b, q0 = 0.0f, q1 = 0.0f;
            #pragma unroll
            for (int k4 = 0; k4 < 16; k4 += 2) {
                float4 w = w4[k4];
                float4 ha = h0[k4], hb = h1[k4];
                p0 += w.x * ha.x + w.y * ha.y + w.z * ha.z + w.w * ha.w;
                p1 += w.x * hb.x + w.y * hb.y + w.z * hb.z + w.w * hb.w;
                float4 w2 = w4[k4 + 1];
                float4 hc = h0[k4 + 1], hd = h1[k4 + 1];
                q0 += w2.x * hc.x + w2.y * hc.y + w2.z * hc.z + w2.w * hc.w;
                q1 += w2.x * hd.x + w2.y * hd.y + w2.z * hd.z + w2.w * hd.w;
            }
            g_amp[(rowbase + r0) * NOSC + lane] = softplusf(p0 + q0);
            g_amp[(rowbase + r1) * NOSC + lane] = softplusf(p1 + q1);
        }
    }
}

// ---------------------------------------------------------------------------
// Evolve: 5 Kuramoto steps, one warp per row. Writes flat A.
// ---------------------------------------------------------------------------
__global__ void evolve_kernel() {
    int gw   = (blockIdx.x * blockDim.x + threadIdx.x) >> 5;
    int lane = threadIdx.x & 31;
    if (gw >= N_DET) return;
    bool act = lane < NOSC;

    float ph = act ? g_phase[gw * NOSC + lane] : 0.0f;
    float am = act ? g_amp[gw * NOSC + lane] : 0.0f;
    float omega = TWO_PI_F * (lane < 4 ? 2.0f : (lane < 12 ? 6.0f : 40.0f));

    #pragma unroll
    for (int s = 0; s < 5; ++s) {
        float c  = act ? cosf(ph) : 0.0f;
        float sn = act ? sinf(ph) : 0.0f;
        float sc = c, ss = sn;
        #pragma unroll
        for (int off = 16; off; off >>= 1) {
            sc += __shfl_down_sync(0xFFFFFFFFu, sc, off);
            ss += __shfl_down_sync(0xFFFFFFFFu, ss, off);
        }
        sc = __shfl_sync(0xFFFFFFFFu, sc, 0);
        ss = __shfl_sync(0xFFFFFFFFu, ss, 0);
        float mc = sc / 28.0f, ms = ss / 28.0f;
        float coup = ms * c - mc * sn;
        ph = mod2pi(ph + 0.01f * (omega + am * coup));
    }
    if (act) {
        float c = cosf(ph), sn = sinf(ph);
        float* arow = g_A + (size_t)gw * 112;
        arow[2 * lane]     = c;  arow[2 * lane + 1]    = c;
        arow[56 + 2*lane]  = sn; arow[56 + 2*lane + 1] = sn;
    }
}

// ---------------------------------------------------------------------------
// Similarity GEMM: 64x256 tile per block, 256 threads, 8 rows x 4 sections
// per thread. Same index math as the PASSING R4 kernel, rows halved so
// 2 blocks/SM (16 warps) fit -> latency hiding for the FFMA2 stream.
// ---------------------------------------------------------------------------
#define GEMM_SMEM_BYTES ((64*112 + 56*256) * 4)

__global__ __launch_bounds__(256, 2)
void gemm_kernel(float* __restrict__ sim) {
    extern __shared__ float smg[];
    float* As = smg;                 // 64 rows x 112 (flat dup pairs)
    float* Bs = smg + 64 * 112;      // 56 k-rows x 256 cols (flat)

    const int tid = threadIdx.x;
    const int tx = tid & 31;
    const int ty = tid >> 5;         // 8 warps -> 8 row groups of 8

    {
        const float4* gA = (const float4*)(g_A + (size_t)blockIdx.y * 64 * 112);
        float4* sA = (float4*)As;
        #pragma unroll
        for (int i = 0; i < 7; ++i) sA[tid + i * 256] = gA[tid + i * 256];

        float4* sB = (float4*)Bs;
        #pragma unroll
        for (int i = 0; i < 14; ++i) {
            int idx = tid + i * 256;            // 0..3583
            int k = idx >> 6, jq = idx & 63;
            sB[idx] = *(const float4*)(g_B + (size_t)k * N_DET + blockIdx.x * 256 + jq * 4);
        }
    }
    __syncthreads();

    unsigned long long acc[8][4];
    #pragma unroll
    for (int r = 0; r < 8; ++r)
        #pragma unroll
        for (int s = 0; s < 4; ++s) acc[r][s] = 0ull;

    #pragma unroll 2
    for (int kp = 0; kp < 28; ++kp) {
        const float* b0 = Bs + (2 * kp) * 256;       // flat row 2kp
        const float* b1 = b0 + 256;                  // flat row 2kp+1
        unsigned long long bc[4], bs[4];
        #pragma unroll
        for (int s = 0; s < 4; ++s) {
            bc[s] = *(const unsigned long long*)(b0 + s * 64 + tx * 2);
            bs[s] = *(const unsigned long long*)(b1 + s * 64 + tx * 2);
        }
        #pragma unroll
        for (int r = 0; r < 8; ++r) {
            ulonglong2 av = *(const ulonglong2*)(As + (ty * 8 + r) * 112 + 4 * kp);
            #pragma unroll
            for (int s = 0; s < 4; ++s) {
                ffma2(acc[r][s], av.x, bc[s]);
                ffma2(acc[r][s], av.y, bs[s]);
            }
        }
    }

    const float invden = 1.0f / DENOM_F;
    #pragma unroll
    for (int r = 0; r < 8; ++r) {
        int grow = blockIdx.y * 64 + ty * 8 + r;
        unsigned long long best = 0ull;
        #pragma unroll
        for (int s = 0; s < 4; ++s) {
            float2 v = *(float2*)&acc[r][s];
            v.x *= invden; v.y *= invden;
            int gcol = blockIdx.x * 256 + s * 64 + tx * 2;
            *(float2*)(sim + (size_t)grow * N_DET + gcol) = v;
            unsigned long long k0 = ((unsigned long long)ordf(v.x) << 32) | (unsigned)(~(unsigned)gcol);
            unsigned long long k1 = ((unsigned long long)ordf(v.y) << 32) | (unsigned)(~(unsigned)(gcol + 1));
            unsigned long long kk = (k0 > k1) ? k0 : k1;
            if (kk > best) best = kk;
        }
        #pragma unroll
        for (int off = 16; off; off >>= 1) {
            unsigned long long o = __shfl_down_sync(0xFFFFFFFFu, best, off);
            if (o > best) best = o;
        }
        if (tx == 0) atomicMax(&g_rowbest[grow], best);
    }
}

// ---------------------------------------------------------------------------
// Parallel greedy match (exact equivalent of the sequential scan).
// ---------------------------------------------------------------------------
__global__ void claim_kernel() {
    int i = blockIdx.x * blockDim.x + threadIdx.x;
    if (i >= N_DET) return;
    const unsigned ORD_THR = __float_as_uint(0.3f) | 0x80000000u;
    unsigned long long rb = g_rowbest[i];
    unsigned ordsim = (unsigned)(rb >> 32);
    if (ordsim > ORD_THR) {
        unsigned j = ~(unsigned)rb;
        unsigned long long claimkey = (rb & 0xFFFFFFFF00000000ull) | (unsigned)(~(unsigned)i);
        atomicMax(&g_colbest[j], claimkey);
    }
}

__global__ void resolve_kernel(float* __restrict__ matches) {
    int i = blockIdx.x * blockDim.x + threadIdx.x;
    if (i >= N_DET) return;
    const unsigned ORD_THR = __float_as_uint(0.3f) | 0x80000000u;
    unsigned long long rb = g_rowbest[i];
    unsigned ordsim = (unsigned)(rb >> 32);
    float m = -1.0f;
    if (ordsim > ORD_THR) {
        unsigned j = ~(unsigned)rb;
        unsigned long long claimkey = (rb & 0xFFFFFFFF00000000ull) | (unsigned)(~(unsigned)i);
        if (g_colbest[j] == claimkey) m = (float)j;
    }
    matches[i] = m;
}

// ---------------------------------------------------------------------------
extern "C" void kernel_launch(void* const* d_in, const int* in_sizes, int n_in,
                              void* d_out, int out_size) {
    const float* det_t  = (const float*)d_in[0];
    const float* det_t1 = (const float*)d_in[1];
    const float* Wp1 = (const float*)d_in[2];
    const float* bp1 = (const float*)d_in[3];
    const float* Wp2 = (const float*)d_in[4];
    const float* bp2 = (const float*)d_in[5];
    const float* Wa1 = (const float*)d_in[6];
    const float* ba1 = (const float*)d_in[7];
    const float* Wa2 = (const float*)d_in[8];
    const float* ba2 = (const float*)d_in[9];
    float* out = (float*)d_out;                 // [0,4096): matches, then sim

    cudaFuncSetAttribute(encode_kernel, cudaFuncAttributeMaxDynamicSharedMemorySize,
                         ENC_SMEM_FLOATS * 4);
    cudaFuncSetAttribute(gemm_kernel, cudaFuncAttributeMaxDynamicSharedMemorySize,
                         GEMM_SMEM_BYTES);

    init_kernel<<<16, 256>>>();
    encode_kernel<<<256, 256, ENC_SMEM_FLOATS * 4>>>(det_t, det_t1,
                                                     Wp1, bp1, Wp2, bp2,
                                                     Wa1, ba1, Wa2, ba2);
    evolve_kernel<<<512, 256>>>();
    gemm_kernel<<<dim3(16, 64), 256, GEMM_SMEM_BYTES>>>(out + N_DET);
    claim_kernel<<<16, 256>>>();
    resolve_kernel<<<16, 256>>>(out);
}

// round 7
// speedup vs baseline: 1.3425x; 1.1278x over previous
#include <cuda_runtime.h>
#include <cuda_bf16.h>
#include <cstdint>

// ---------------------------------------------------------------------------
// PhaseTracker: encode -> evolve -> HMMA bf16-split GEMM -> parallel greedy
// ---------------------------------------------------------------------------

#define N_DET   4096
#define DIM     128
#define HID     64
#define NOSC    28
#define KGEMM   192          // 3 blocks of 56 (hi|hi|lo vs hi|lo|hi) padded
#define KTILES  11           // k < 176 (data ends at 168, [168,176) zeroed)
#define TWO_PI_F 6.283185307179586f
#define INV_2PI  0.15915494309189535f
#define DENOM_F  28.000010583006244f   // (sqrt(28)+1e-6)^2

__device__ float g_phase[N_DET * NOSC];
__device__ float g_amp[N_DET * NOSC];
__device__ __align__(16) __nv_bfloat16 g_Abf[N_DET * KGEMM];  // [row][k]: [hi56|hi56|lo56|pad]
__device__ __align__(16) __nv_bfloat16 g_Bbf[N_DET * KGEMM];  // [row][k]: [hi56|lo56|hi56|pad]
__device__ unsigned long long g_rowbest[N_DET];
__device__ unsigned long long g_colbest[N_DET];

__device__ __forceinline__ float mod2pi(float v) {
    return v - floorf(v * INV_2PI) * TWO_PI_F;
}
__device__ __forceinline__ float softplusf(float x) {
    return fmaxf(x, 0.0f) + log1pf(expf(-fabsf(x)));
}
__device__ __forceinline__ unsigned ordf(float x) {
    unsigned u = __float_as_uint(x);
    return (u & 0x80000000u) ? ~u : (u | 0x80000000u);
}
__device__ __forceinline__ void bf16split(float v, __nv_bfloat16& hi, __nv_bfloat16& lo) {
    hi = __float2bfloat16_rn(v);
    lo = __float2bfloat16_rn(v - __bfloat162float(hi));
}
__device__ __forceinline__ uint32_t smem_u32(const void* p) {
    uint32_t a;
    asm("{ .reg .u64 t; cvta.to.shared.u64 t, %1; cvt.u32.u64 %0, t; }" : "=r"(a) : "l"(p));
    return a;
}
__device__ __forceinline__ void ldm_x4(uint32_t* r, uint32_t addr) {
    asm volatile("ldmatrix.sync.aligned.m8n8.x4.shared.b16 {%0,%1,%2,%3}, [%4];"
                 : "=r"(r[0]), "=r"(r[1]), "=r"(r[2]), "=r"(r[3]) : "r"(addr));
}
__device__ __forceinline__ void ldm_x2(uint32_t* r, uint32_t addr) {
    asm volatile("ldmatrix.sync.aligned.m8n8.x2.shared.b16 {%0,%1}, [%2];"
                 : "=r"(r[0]), "=r"(r[1]) : "r"(addr));
}
__device__ __forceinline__ void mma16816(float* c, const uint32_t* a, const uint32_t* b) {
    asm volatile("mma.sync.aligned.m16n8k16.row.col.f32.bf16.bf16.f32 "
                 "{%0,%1,%2,%3}, {%4,%5,%6,%7}, {%8,%9}, {%0,%1,%2,%3};"
                 : "+f"(c[0]), "+f"(c[1]), "+f"(c[2]), "+f"(c[3])
                 : "r"(a[0]), "r"(a[1]), "r"(a[2]), "r"(a[3]), "r"(b[0]), "r"(b[1]));
}

// ---------------------------------------------------------------------------
__global__ void init_kernel() {
    int i = blockIdx.x * blockDim.x + threadIdx.x;
    if (i < N_DET) {
        g_rowbest[i] = 0ull; g_colbest[i] = 0ull;
        uint4 z = make_uint4(0, 0, 0, 0);
        uint4* pa = (uint4*)((char*)g_Abf + (size_t)i * 384 + 336);
        uint4* pb = (uint4*)((char*)g_Bbf + (size_t)i * 384 + 336);
        pa[0] = z; pa[1] = z; pa[2] = z;
        pb[0] = z; pb[1] = z; pb[2] = z;
    }
}

// ---------------------------------------------------------------------------
// Encode (R5-proven structure): two rows per weight read.
// ---------------------------------------------------------------------------
#define ENC_W1STR 132
#define ENC_W2STR 68
#define ENC_SMEM_FLOATS (2*HID*ENC_W1STR + 2*NOSC*ENC_W2STR + 512 + 512)

__global__ __launch_bounds__(256, 2)
void encode_kernel(const float* __restrict__ det_t, const float* __restrict__ det_t1,
                   const float* __restrict__ Wp1, const float* __restrict__ bp1,
                   const float* __restrict__ Wp2, const float* __restrict__ bp2,
                   const float* __restrict__ Wa1, const float* __restrict__ ba1,
                   const float* __restrict__ Wa2, const float* __restrict__ ba2) {
    extern __shared__ float sm[];
    float* wp1T = sm;
    float* wa1T = wp1T + HID * ENC_W1STR;
    float* wp2T = wa1T + HID * ENC_W1STR;
    float* wa2T = wp2T + NOSC * ENC_W2STR;
    float* xs   = wa2T + NOSC * ENC_W2STR;     // 4 x 128
    float* hs   = xs + 512;                    // 4 x 128

    int tid = threadIdx.x;
    for (int idx = tid; idx < DIM * HID; idx += 256) {
        int k = idx >> 6, j = idx & 63;
        wp1T[j * ENC_W1STR + k] = Wp1[idx];
        wa1T[j * ENC_W1STR + k] = Wa1[idx];
    }
    for (int idx = tid; idx < HID * NOSC; idx += 256) {
        int k = idx / NOSC, j = idx % NOSC;
        wp2T[j * ENC_W2STR + k] = Wp2[idx];
        wa2T[j * ENC_W2STR + k] = Wa2[idx];
    }

    const int quad = tid >> 7;
    const int t    = tid & 127;
    const int r0 = 2 * quad, r1 = r0 + 1;

    for (int it = 0; it < 8; ++it) {
        int rowbase = blockIdx.x * 32 + it * 4;
        bool isT = rowbase < N_DET;
        const float* X = isT ? (det_t + (size_t)rowbase * DIM)
                             : (det_t1 + (size_t)(rowbase - N_DET) * DIM);
        __syncthreads();
        if (tid < 128) {
            ((float4*)xs)[tid] = ((const float4*)X)[tid];
        }
        __syncthreads();

        {
            bool doAmp = (t >= 64);
            if (!doAmp || isT) {
                int j = doAmp ? (t - 64) : t;
                const float4* w4 = (const float4*)(doAmp ? &wa1T[j * ENC_W1STR]
                                                         : &wp1T[j * ENC_W1STR]);
                const float4* x0 = (const float4*)(xs + r0 * 128);
                const float4* x1 = (const float4*)(xs + r1 * 128);
                float b = doAmp ? ba1[j] : bp1[j];
                float a0 = b, a1 = b, c0 = 0.0f, c1 = 0.0f;
                #pragma unroll
                for (int k4 = 0; k4 < 32; k4 += 2) {
                    float4 w = w4[k4];
                    float4 xa = x0[k4], xb = x1[k4];
                    a0 += w.x * xa.x + w.y * xa.y + w.z * xa.z + w.w * xa.w;
                    a1 += w.x * xb.x + w.y * xb.y + w.z * xb.z + w.w * xb.w;
                    float4 w2 = w4[k4 + 1];
                    float4 xc = x0[k4 + 1], xd = x1[k4 + 1];
                    c0 += w2.x * xc.x + w2.y * xc.y + w2.z * xc.z + w2.w * xc.w;
                    c1 += w2.x * xd.x + w2.y * xd.y + w2.z * xd.z + w2.w * xd.w;
                }
                hs[r0 * 128 + t] = fmaxf(a0 + c0, 0.0f);
                hs[r1 * 128 + t] = fmaxf(a1 + c1, 0.0f);
            }
        }
        __syncthreads();

        int lane = t & 31, wgrp = t >> 5;
        if (wgrp == 0 && lane < NOSC) {               // phase head
            const float4* w4 = (const float4*)&wp2T[lane * ENC_W2STR];
            const float4* h0 = (const float4*)(hs + r0 * 128);
            const float4* h1 = (const float4*)(hs + r1 * 128);
            float b = bp2[lane];
            float p0 = b, p1 = b, q0 = 0.0f, q1 = 0.0f;
            #pragma unroll
            for (int k4 = 0; k4 < 16; k4 += 2) {
                float4 w = w4[k4];
                float4 ha = h0[k4], hb = h1[k4];
                p0 += w.x * ha.x + w.y * ha.y + w.z * ha.z + w.w * ha.w;
                p1 += w.x * hb.x + w.y * hb.y + w.z * hb.z + w.w * hb.w;
                float4 w2 = w4[k4 + 1];
                float4 hc = h0[k4 + 1], hd = h1[k4 + 1];
                q0 += w2.x * hc.x + w2.y * hc.y + w2.z * hc.z + w2.w * hc.w;
                q1 += w2.x * hd.x + w2.y * hd.y + w2.z * hd.z + w2.w * hd.w;
            }
            float ph0 = mod2pi(p0 + q0), ph1 = mod2pi(p1 + q1);
            int gr0 = rowbase + r0, gr1 = rowbase + r1;
            if (isT) {
                g_phase[gr0 * NOSC + lane] = ph0;
                g_phase[gr1 * NOSC + lane] = ph1;
            } else {
                // B' row layout: [cos_hi28 sin_hi28 | cos_lo28 sin_lo28 | cos_hi28 sin_hi28]
                int cc0 = gr0 - N_DET, cc1 = gr1 - N_DET;
                float cv0 = cosf(ph0), sv0 = sinf(ph0);
                float cv1 = cosf(ph1), sv1 = sinf(ph1);
                __nv_bfloat16 chi, clo, shi, slo;
                __nv_bfloat16* br;
                br = g_Bbf + (size_t)cc0 * KGEMM;
                bf16split(cv0, chi, clo); bf16split(sv0, shi, slo);
                br[lane] = chi;       br[28 + lane] = shi;
                br[56 + lane] = clo;  br[84 + lane] = slo;
                br[112 + lane] = chi; br[140 + lane] = shi;
                br = g_Bbf + (size_t)cc1 * KGEMM;
                bf16split(cv1, chi, clo); bf16split(sv1, shi, slo);
                br[lane] = chi;       br[28 + lane] = shi;
                br[56 + lane] = clo;  br[84 + lane] = slo;
                br[112 + lane] = chi; br[140 + lane] = shi;
            }
        } else if (wgrp == 1 && lane < NOSC && isT) { // amp head
            const float4* w4 = (const float4*)&wa2T[lane * ENC_W2STR];
            const float4* h0 = (const float4*)(hs + r0 * 128 + 64);
            const float4* h1 = (const float4*)(hs + r1 * 128 + 64);
            float b = ba2[lane];
            float p0 = b, p1 = b, q0 = 0.0f, q1 = 0.0f;
            #pragma unroll
            for (int k4 = 0; k4 < 16; k4 += 2) {
                float4 w = w4[k4];
                float4 ha = h0[k4], hb = h1[k4];
                p0 += w.x * ha.x + w.y * ha.y + w.z * ha.z + w.w * ha.w;
                p1 += w.x * hb.x + w.y * hb.y + w.z * hb.z + w.w * hb.w;
                float4 w2 = w4[k4 + 1];
                float4 hc = h0[k4 + 1], hd = h1[k4 + 1];
                q0 += w2.x * hc.x + w2.y * hc.y + w2.z * hc.z + w2.w * hc.w;
                q1 += w2.x * hd.x + w2.y * hd.y + w2.z * hd.z + w2.w * hd.w;
            }
            g_amp[(rowbase + r0) * NOSC + lane] = softplusf(p0 + q0);
            g_amp[(rowbase + r1) * NOSC + lane] = softplusf(p1 + q1);
        }
    }
}

// ---------------------------------------------------------------------------
// Evolve: 5 Kuramoto steps, one warp per row. Writes A' bf16 rows.
// A' row layout: [cos_hi28 sin_hi28 | cos_hi28 sin_hi28 | cos_lo28 sin_lo28]
// ---------------------------------------------------------------------------
__global__ void evolve_kernel() {
    int gw   = (blockIdx.x * blockDim.x + threadIdx.x) >> 5;
    int lane = threadIdx.x & 31;
    if (gw >= N_DET) return;
    bool act = lane < NOSC;

    float ph = act ? g_phase[gw * NOSC + lane] : 0.0f;
    float am = act ? g_amp[gw * NOSC + lane] : 0.0f;
    float omega = TWO_PI_F * (lane < 4 ? 2.0f : (lane < 12 ? 6.0f : 40.0f));

    #pragma unroll
    for (int s = 0; s < 5; ++s) {
        float c  = act ? cosf(ph) : 0.0f;
        float sn = act ? sinf(ph) : 0.0f;
        float sc = c, ss = sn;
        #pragma unroll
        for (int off = 16; off; off >>= 1) {
            sc += __shfl_down_sync(0xFFFFFFFFu, sc, off);
            ss += __shfl_down_sync(0xFFFFFFFFu, ss, off);
        }
        sc = __shfl_sync(0xFFFFFFFFu, sc, 0);
        ss = __shfl_sync(0xFFFFFFFFu, ss, 0);
        float mc = sc / 28.0f, ms = ss / 28.0f;
        float coup = ms * c - mc * sn;
        ph = mod2pi(ph + 0.01f * (omega + am * coup));
    }
    if (act) {
        float c = cosf(ph), sn = sinf(ph);
        __nv_bfloat16 chi, clo, shi, slo;
        bf16split(c, chi, clo); bf16split(sn, shi, slo);
        __nv_bfloat16* ar = g_Abf + (size_t)gw * KGEMM;
        ar[lane] = chi;       ar[28 + lane] = shi;
        ar[56 + lane] = chi;  ar[84 + lane] = shi;
        ar[112 + lane] = clo; ar[140 + lane] = slo;
    }
}

// ---------------------------------------------------------------------------
// HMMA GEMM: 128x128 tile/CTA, 8 warps (2x4), warp = 64x32 via m16n8k16.
// SMEM rows padded to 400 B -> conflict-free ldmatrix. Fused rowbest.
// ---------------------------------------------------------------------------
#define GT_ROWB   400                       // bytes per smem row (192*2 + 16 pad)
#define GT_TILE   (128 * GT_ROWB)           // 51200
#define GT_SMEM_TOTAL (2 * GT_TILE)         // 102400

__global__ __launch_bounds__(256, 1)
void gemm_kernel(float* __restrict__ sim) {
    extern __shared__ char smg[];
    const int tid = threadIdx.x;
    const int lane = tid & 31;
    const int w = tid >> 5;
    const int warpRow = w >> 2;       // 0..1  (64 rows each)
    const int warpCol = w & 3;        // 0..3  (32 cols each)
    uint32_t smA = smem_u32(smg);
    uint32_t smB = smA + GT_TILE;

    // ---- stage tiles (row-major, padded stride) ----
    {
        const uint4* srcA = (const uint4*)(g_Abf + (size_t)blockIdx.y * 128 * KGEMM);
        const uint4* srcB = (const uint4*)(g_Bbf + (size_t)blockIdx.x * 128 * KGEMM);
        #pragma unroll
        for (int i = 0; i < 12; ++i) {
            int idx = tid + i * 256;          // 0..3071
            int r = idx / 24, q = idx - r * 24;
            int off = r * GT_ROWB + q * 16;
            *(uint4*)(smg + off) = srcA[idx];
            *(uint4*)(smg + GT_TILE + off) = srcB[idx];
        }
    }
    __syncthreads();

    float acc[4][4][4];
    #pragma unroll
    for (int mt = 0; mt < 4; ++mt)
        #pragma unroll
        for (int nt = 0; nt < 4; ++nt)
            #pragma unroll
            for (int e = 0; e < 4; ++e) acc[mt][nt][e] = 0.0f;

    const uint32_t aBase = smA + (warpRow * 64 + (lane & 15)) * GT_ROWB + (lane >> 4) * 16;
    const uint32_t bBase = smB + (warpCol * 32 + (lane & 7)) * GT_ROWB + ((lane >> 3) & 1) * 16;

    #pragma unroll
    for (int kt = 0; kt < KTILES; ++kt) {
        uint32_t af[4][4], bf[4][2];
        #pragma unroll
        for (int mt = 0; mt < 4; ++mt)
            ldm_x4(af[mt], aBase + mt * 16 * GT_ROWB + kt * 32);
        #pragma unroll
        for (int nt = 0; nt < 4; ++nt)
            ldm_x2(bf[nt], bBase + nt * 8 * GT_ROWB + kt * 32);
        #pragma unroll
        for (int mt = 0; mt < 4; ++mt)
            #pragma unroll
            for (int nt = 0; nt < 4; ++nt)
                mma16816(acc[mt][nt], af[mt], bf[nt]);
    }

    // ---- epilogue: scale, store, fused rowbest ----
    const float invden = 1.0f / DENOM_F;
    const int g = lane >> 2, tq = lane & 3;
    const int rowg = blockIdx.y * 128 + warpRow * 64 + g;
    const int colg = blockIdx.x * 128 + warpCol * 32 + tq * 2;

    #pragma unroll
    for (int mt = 0; mt < 4; ++mt) {
        int r0 = rowg + mt * 16;
        int r1 = r0 + 8;
        unsigned long long best0 = 0ull, best1 = 0ull;
        #pragma unroll
        for (int nt = 0; nt < 4; ++nt) {
            int col = colg + nt * 8;
            float2 v0, v1;
            v0.x = acc[mt][nt][0] * invden; v0.y = acc[mt][nt][1] * invden;
            v1.x = acc[mt][nt][2] * invden; v1.y = acc[mt][nt][3] * invden;
            *(float2*)(sim + (size_t)r0 * N_DET + col) = v0;
            *(float2*)(sim + (size_t)r1 * N_DET + col) = v1;
            unsigned long long k;
            k = ((unsigned long long)ordf(v0.x) << 32) | (unsigned)(~(unsigned)col);
            if (k > best0) best0 = k;
            k = ((unsigned long long)ordf(v0.y) << 32) | (unsigned)(~(unsigned)(col + 1));
            if (k > best0) best0 = k;
            k = ((unsigned long long)ordf(v1.x) << 32) | (unsigned)(~(unsigned)col);
            if (k > best1) best1 = k;
            k = ((unsigned long long)ordf(v1.y) << 32) | (unsigned)(~(unsigned)(col + 1));
            if (k > best1) best1 = k;
        }
        // reduce across the 4-lane column group (lanes sharing g)
        #pragma unroll
        for (int off = 1; off < 4; off <<= 1) {
            unsigned long long o0 = __shfl_xor_sync(0xFFFFFFFFu, best0, off);
            unsigned long long o1 = __shfl_xor_sync(0xFFFFFFFFu, best1, off);
            if (o0 > best0) best0 = o0;
            if (o1 > best1) best1 = o1;
        }
        if (tq == 0) {
            atomicMax(&g_rowbest[r0], best0);
            atomicMax(&g_rowbest[r1], best1);
        }
    }
}

// ---------------------------------------------------------------------------
// Parallel greedy match (exact equivalent of the sequential scan).
// ---------------------------------------------------------------------------
__global__ void claim_kernel() {
    int i = blockIdx.x * blockDim.x + threadIdx.x;
    if (i >= N_DET) return;
    const unsigned ORD_THR = __float_as_uint(0.3f) | 0x80000000u;
    unsigned long long rb = g_rowbest[i];
    unsigned ordsim = (unsigned)(rb >> 32);
    if (ordsim > ORD_THR) {
        unsigned j = ~(unsigned)rb;
        unsigned long long claimkey = (rb & 0xFFFFFFFF00000000ull) | (unsigned)(~(unsigned)i);
        atomicMax(&g_colbest[j], claimkey);
    }
}

__global__ void resolve_kernel(float* __restrict__ matches) {
    int i = blockIdx.x * blockDim.x + threadIdx.x;
    if (i >= N_DET) return;
    const unsigned ORD_THR = __float_as_uint(0.3f) | 0x80000000u;
    unsigned long long rb = g_rowbest[i];
    unsigned ordsim = (unsigned)(rb >> 32);
    float m = -1.0f;
    if (ordsim > ORD_THR) {
        unsigned j = ~(unsigned)rb;
        unsigned long long claimkey = (rb & 0xFFFFFFFF00000000ull) | (unsigned)(~(unsigned)i);
        if (g_colbest[j] == claimkey) m = (float)j;
    }
    matches[i] = m;
}

// ---------------------------------------------------------------------------
extern "C" void kernel_launch(void* const* d_in, const int* in_sizes, int n_in,
                              void* d_out, int out_size) {
    const float* det_t  = (const float*)d_in[0];
    const float* det_t1 = (const float*)d_in[1];
    const float* Wp1 = (const float*)d_in[2];
    const float* bp1 = (const float*)d_in[3];
    const float* Wp2 = (const float*)d_in[4];
    const float* bp2 = (const float*)d_in[5];
    const float* Wa1 = (const float*)d_in[6];
    const float* ba1 = (const float*)d_in[7];
    const float* Wa2 = (const float*)d_in[8];
    const float* ba2 = (const float*)d_in[9];
    float* out = (float*)d_out;                 // [0,4096): matches, then sim

    cudaFuncSetAttribute(encode_kernel, cudaFuncAttributeMaxDynamicSharedMemorySize,
                         ENC_SMEM_FLOATS * 4);
    cudaFuncSetAttribute(gemm_kernel, cudaFuncAttributeMaxDynamicSharedMemorySize,
                         GT_SMEM_TOTAL);

    init_kernel<<<16, 256>>>();
    encode_kernel<<<256, 256, ENC_SMEM_FLOATS * 4>>>(det_t, det_t1,
                                                     Wp1, bp1, Wp2, bp2,
                                                     Wa1, ba1, Wa2, ba2);
    evolve_kernel<<<512, 256>>>();
    gemm_kernel<<<dim3(32, 32), 256, GT_SMEM_TOTAL>>>(out + N_DET);
    claim_kernel<<<16, 256>>>();
    resolve_kernel<<<16, 256>>>(out);
}